// round 15
// baseline (speedup 1.0000x reference)
#include <cuda_runtime.h>
#include <cuda_fp16.h>
#include <cstdint>

#define NN 100000
#define CC 256
#define EE_MAX 1600000
#define MBLK ((NN + 127) / 128)
#define SCAN_BLK 98            // ceil(100000/1024)

// ---- scratch (__device__ globals) ----
__device__ int   g_deg[NN];
__device__ int   g_off[NN + 1];
__device__ int   g_cur[NN];
__device__ int   g_src[EE_MAX];
__device__ int   g_bsum[128];
__device__ float g_isd[NN];
__device__ __half g_xs[(size_t)NN * CC];            // (h@W)*isd[node], fp16
__device__ __half g_ah[(size_t)(NN + 128) * CC];    // fp16 copy of z1 (layer-2 GEMM input); padded
__device__ __half g_w1[CC * CC];                    // W1^T [n][k], fp16
__device__ __half g_w2[CC * CC];                    // W2^T [n][k], fp16

// =============== launch 0: convert W (both layers, fp16) + zero deg ===============
__global__ void k_conv_zero(const float* __restrict__ W1, const float* __restrict__ W2) {
    int gi = blockIdx.x * 256 + threadIdx.x;
    if (blockIdx.x < 512) {
        const float* W = (gi < CC * CC) ? W1 : W2;
        int i = gi & (CC * CC - 1);
        int n = i >> 8, k = i & 255;
        __half h = __float2half_rn(W[k * CC + n]);
        if (gi < CC * CC) g_w1[i] = h;
        else              g_w2[i] = h;
    } else {
        int i = gi - 512 * 256;
        if (i < NN) g_deg[i] = 0;
    }
}

// 4 edges/thread histogram
__global__ void k_hist(const int* __restrict__ col, int E) {
    int e = (blockIdx.x * blockDim.x + threadIdx.x) * 4;
    if (e + 4 <= E) {
        int4 c = *(const int4*)(col + e);
        atomicAdd(&g_deg[c.x], 1);
        atomicAdd(&g_deg[c.y], 1);
        atomicAdd(&g_deg[c.z], 1);
        atomicAdd(&g_deg[c.w], 1);
    } else {
        for (; e < E; e++) atomicAdd(&g_deg[col[e]], 1);
    }
}

// scan level 1 + isd
__global__ void __launch_bounds__(1024) k_scan1() {
    __shared__ int sh[1024];
    int i = blockIdx.x * 1024 + threadIdx.x;
    int v = (i < NN) ? g_deg[i] : 0;
    if (i < NN) g_isd[i] = rsqrtf((float)(v + 1));
    sh[threadIdx.x] = v;
    __syncthreads();
    for (int o = 512; o > 0; o >>= 1) {
        if (threadIdx.x < o) sh[threadIdx.x] += sh[threadIdx.x + o];
        __syncthreads();
    }
    if (threadIdx.x == 0) g_bsum[blockIdx.x] = sh[0];
}
// scan level 2 folded into level 3
__global__ void __launch_bounds__(1024) k_scan3() {
    __shared__ int sh[1024];
    __shared__ int sb[128];
    __shared__ int base_s;
    if (threadIdx.x < 128) sb[threadIdx.x] = (threadIdx.x < SCAN_BLK) ? g_bsum[threadIdx.x] : 0;
    __syncthreads();
    if (threadIdx.x == 0) {
        int c = 0;
        for (int j = 0; j < (int)blockIdx.x; j++) c += sb[j];
        base_s = c;
        if (blockIdx.x == 0) {
            int tot = 0;
            for (int j = 0; j < SCAN_BLK; j++) tot += sb[j];
            g_off[NN] = tot;
        }
    }
    int i = blockIdx.x * 1024 + threadIdx.x;
    int v = (i < NN) ? g_deg[i] : 0;
    sh[threadIdx.x] = v;
    __syncthreads();
    for (int o = 1; o < 1024; o <<= 1) {
        int u = (threadIdx.x >= o) ? sh[threadIdx.x - o] : 0;
        __syncthreads();
        sh[threadIdx.x] += u;
        __syncthreads();
    }
    if (i < NN) {
        int excl = base_s + sh[threadIdx.x] - v;
        g_off[i] = excl;
        g_cur[i] = excl;
    }
}
// 4 edges/thread fill
__global__ void k_fill(const int* __restrict__ row, const int* __restrict__ col, int E) {
    int e = (blockIdx.x * blockDim.x + threadIdx.x) * 4;
    if (e + 4 <= E) {
        int4 r = *(const int4*)(row + e);
        int4 c = *(const int4*)(col + e);
        int p0 = atomicAdd(&g_cur[c.x], 1); if (p0 < EE_MAX) g_src[p0] = r.x;
        int p1 = atomicAdd(&g_cur[c.y], 1); if (p1 < EE_MAX) g_src[p1] = r.y;
        int p2 = atomicAdd(&g_cur[c.z], 1); if (p2 < EE_MAX) g_src[p2] = r.z;
        int p3 = atomicAdd(&g_cur[c.w], 1); if (p3 < EE_MAX) g_src[p3] = r.w;
    } else {
        for (; e < E; e++) {
            int pos = atomicAdd(&g_cur[col[e]], 1);
            if (pos < EE_MAX) g_src[pos] = row[e];
        }
    }
}

// =============== warp-MMA GEMM: block 128M x 256N, 64x64 warp tiles ===============
#define KPAD 40                 // fp16 row stride 80B -> ldmatrix conflict-free
#define ABUF (128 * KPAD)       // A tile elements
#define BBUF (256 * KPAD)       // B tile elements
#define BUFSTR (ABUF + BBUF)    // per-buffer stride

__device__ __forceinline__ void mma_f16(float* c, const uint32_t* a, const uint32_t* b) {
    asm volatile(
        "mma.sync.aligned.m16n8k16.row.col.f32.f16.f16.f32 "
        "{%0,%1,%2,%3}, {%4,%5,%6,%7}, {%8,%9}, {%0,%1,%2,%3};"
        : "+f"(c[0]), "+f"(c[1]), "+f"(c[2]), "+f"(c[3])
        : "r"(a[0]), "r"(a[1]), "r"(a[2]), "r"(a[3]), "r"(b[0]), "r"(b[1]));
}
__device__ __forceinline__ void ldsm4(uint32_t* r, uint32_t a) {
    asm volatile("ldmatrix.sync.aligned.m8n8.x4.shared.b16 {%0,%1,%2,%3}, [%4];"
                 : "=r"(r[0]), "=r"(r[1]), "=r"(r[2]), "=r"(r[3]) : "r"(a));
}
__device__ __forceinline__ void cpasync16(uint32_t dst, const void* src) {
    asm volatile("cp.async.cg.shared.global [%0], [%1], 16;" :: "r"(dst), "l"(src));
}
#define CP_COMMIT() asm volatile("cp.async.commit_group;" ::: "memory")
#define CP_WAIT0()  asm volatile("cp.async.wait_group 0;" ::: "memory")

template <bool HALF_A>
__global__ void __launch_bounds__(256, 1) k_gemm_mma(const float* __restrict__ A) {
    const __half* __restrict__ W = HALF_A ? g_w2 : g_w1;

    extern __shared__ __half smem[];
    const uint32_t sbase = (uint32_t)__cvta_generic_to_shared(smem);

    const int tid = threadIdx.x;
    const int wid = tid >> 5;
    const int lane = tid & 31;
    const int brow = blockIdx.y * 128;
    const int wm = (wid & 1) * 64;       // 2 m-warps
    const int wn = (wid >> 1) * 64;      // 4 n-warps

    float acc[4][8][4];
#pragma unroll
    for (int i = 0; i < 4; i++)
#pragma unroll
        for (int j = 0; j < 8; j++)
#pragma unroll
            for (int l = 0; l < 4; l++) acc[i][j][l] = 0.0f;

    const int ar = tid >> 1;             // A fp32 stage row 0..127
    const int aq = tid & 1;              // float4 parity
    const int br = tid >> 2;             // stage row 0..63 (x4 passes for B)
    const int bq = tid & 3;              // uint4 within 32-k chunk
    const bool arow_ok = (brow + ar) < NN;
    const float* Abase = A + (size_t)(brow + ar) * CC;
    const __half* AHbase = g_ah + (size_t)(brow + br) * CC + bq * 8;
    const __half* WBbase = W + (size_t)br * CC + bq * 8;
    const uint32_t sto = (uint32_t)(br * (KPAD * 2) + bq * 16);

    const uint32_t aoff = (uint32_t)((wm + (lane & 15)) * (KPAD * 2) + ((lane >> 4) * 8) * 2);
    const uint32_t boff = (uint32_t)((wn + (lane & 7) + ((lane >> 4) & 1) * 8) * (KPAD * 2)
                                     + (((lane >> 3) & 1) * 8) * 2);

    float4 pf[4];
#pragma unroll
    for (int p = 0; p < 4; p++) pf[p] = make_float4(0.f, 0.f, 0.f, 0.f);

    // stage chunk 0
    if (!HALF_A) {
        if (arow_ok) {
#pragma unroll
            for (int p = 0; p < 4; p++) pf[p] = *(const float4*)(Abase + (aq + p * 2) * 4);
        }
    } else {
#pragma unroll
        for (int p = 0; p < 2; p++)
            cpasync16(sbase + sto + p * 64 * (KPAD * 2), AHbase + (size_t)(p * 64) * CC);
    }
    {
        const uint32_t b0 = sbase + ABUF * 2;
#pragma unroll
        for (int p = 0; p < 4; p++)
            cpasync16(b0 + sto + p * 64 * (KPAD * 2), WBbase + (size_t)(p * 64) * CC);
        CP_COMMIT();
    }

    for (int kc = 0; kc < 8; kc++) {
        const uint32_t cb = (uint32_t)(kc & 1) * BUFSTR * 2;
        __half* As = smem + (kc & 1) * BUFSTR;

        if (!HALF_A) {
#pragma unroll
            for (int p = 0; p < 4; p++) {
                int q = aq + p * 2;
                float4 v = pf[p];
                *(__half2*)(As + ar * KPAD + q * 4)     = __floats2half2_rn(v.x, v.y);
                *(__half2*)(As + ar * KPAD + q * 4 + 2) = __floats2half2_rn(v.z, v.w);
            }
        }
        CP_WAIT0();
        __syncthreads();

        if (kc < 7) {
            const int k1 = (kc + 1) * 32;
            const uint32_t ob = (uint32_t)((kc + 1) & 1) * BUFSTR * 2;
            if (!HALF_A) {
                if (arow_ok) {
#pragma unroll
                    for (int p = 0; p < 4; p++)
                        pf[p] = *(const float4*)(Abase + k1 + (aq + p * 2) * 4);
                }
            } else {
#pragma unroll
                for (int p = 0; p < 2; p++)
                    cpasync16(sbase + ob + sto + p * 64 * (KPAD * 2),
                              AHbase + (size_t)(p * 64) * CC + k1);
            }
            const uint32_t nb = sbase + ob + ABUF * 2;
#pragma unroll
            for (int p = 0; p < 4; p++)
                cpasync16(nb + sto + p * 64 * (KPAD * 2), WBbase + (size_t)(p * 64) * CC + k1);
            CP_COMMIT();
        }

        const uint32_t sA = sbase + cb;
        const uint32_t sB = sbase + cb + ABUF * 2;
#pragma unroll
        for (int ks = 0; ks < 32; ks += 16) {
            const uint32_t ksb = (uint32_t)(ks * 2);
            uint32_t ah[4][4];
#pragma unroll
            for (int mf = 0; mf < 4; mf++)
                ldsm4(ah[mf], sA + aoff + mf * 16 * (KPAD * 2) + ksb);
#pragma unroll
            for (int nfp = 0; nfp < 4; nfp++) {
                uint32_t bh[4];
                ldsm4(bh, sB + boff + nfp * 16 * (KPAD * 2) + ksb);
#pragma unroll
                for (int half = 0; half < 2; half++) {
                    int nf = nfp * 2 + half;
#pragma unroll
                    for (int mf = 0; mf < 4; mf++)
                        mma_f16(acc[mf][nf], ah[mf], bh + half * 2);
                }
            }
        }
    }

    // epilogue: scale by isd[row], store fp16 (warp writes 64 rows x 64 cols)
    const int fr = lane >> 2;
    const int fc = (lane & 3) * 2;
#pragma unroll
    for (int mf = 0; mf < 4; mf++) {
#pragma unroll
        for (int half = 0; half < 2; half++) {
            int grow = brow + wm + mf * 16 + half * 8 + fr;
            if (grow < NN) {
                float s = g_isd[grow];
                __half* dst = g_xs + (size_t)grow * CC + wn + fc;
#pragma unroll
                for (int nf = 0; nf < 8; nf++) {
                    *(__half2*)(dst + nf * 8) = __floats2half2_rn(
                        acc[mf][nf][half * 2 + 0] * s,
                        acc[mf][nf][half * 2 + 1] * s);
                }
            }
        }
    }
}
#define GEMM_SMEM (2 * BUFSTR * 2)    // 61440 bytes

// =============== aggregation + LayerNorm + ReLU (4 warps/block, warp per node) ===============
__device__ __forceinline__ void add8h(float* a, uint4 v) {
    const __half2* h = (const __half2*)&v;
#pragma unroll
    for (int i = 0; i < 4; i++) {
        float2 f = __half22float2(h[i]);
        a[2 * i]     += f.x;
        a[2 * i + 1] += f.y;
    }
}

__global__ void __launch_bounds__(128) k_agg_ln(const float* __restrict__ b,
                                                const float* __restrict__ gamma,
                                                const float* __restrict__ beta,
                                                float* __restrict__ out,
                                                int write_h) {
    const int v = blockIdx.x * 4 + (threadIdx.x >> 5);
    if (v >= NN) return;
    const int t = threadIdx.x & 31;
    const int c8 = t * 8;

    const uint4* xs16 = (const uint4*)g_xs;
    float acc[8];
#pragma unroll
    for (int i = 0; i < 8; i++) acc[i] = 0.0f;
    add8h(acc, xs16[(size_t)v * 32 + t]);

    int e = g_off[v];
    const int end = g_off[v + 1];
    for (; e + 8 <= end; e += 8) {
        uint4 x0 = xs16[(size_t)g_src[e]     * 32 + t];
        uint4 x1 = xs16[(size_t)g_src[e + 1] * 32 + t];
        uint4 x2 = xs16[(size_t)g_src[e + 2] * 32 + t];
        uint4 x3 = xs16[(size_t)g_src[e + 3] * 32 + t];
        uint4 x4 = xs16[(size_t)g_src[e + 4] * 32 + t];
        uint4 x5 = xs16[(size_t)g_src[e + 5] * 32 + t];
        uint4 x6 = xs16[(size_t)g_src[e + 6] * 32 + t];
        uint4 x7 = xs16[(size_t)g_src[e + 7] * 32 + t];
        add8h(acc, x0); add8h(acc, x1); add8h(acc, x2); add8h(acc, x3);
        add8h(acc, x4); add8h(acc, x5); add8h(acc, x6); add8h(acc, x7);
    }
    for (; e < end; e++) add8h(acc, xs16[(size_t)g_src[e] * 32 + t]);

    const float s = g_isd[v];
    float4 bb0 = *(const float4*)(b + c8);
    float4 bb1 = *(const float4*)(b + c8 + 4);
    float h[8];
    h[0] = acc[0] * s + bb0.x; h[1] = acc[1] * s + bb0.y;
    h[2] = acc[2] * s + bb0.z; h[3] = acc[3] * s + bb0.w;
    h[4] = acc[4] * s + bb1.x; h[5] = acc[5] * s + bb1.y;
    h[6] = acc[6] * s + bb1.z; h[7] = acc[7] * s + bb1.w;

    float part = 0.f;
#pragma unroll
    for (int i = 0; i < 8; i++) part += h[i];
#pragma unroll
    for (int o = 16; o > 0; o >>= 1) part += __shfl_xor_sync(0xffffffffu, part, o);
    const float mu = part * (1.0f / 256.0f);

    float d[8];
    float part2 = 0.f;
#pragma unroll
    for (int i = 0; i < 8; i++) { d[i] = h[i] - mu; part2 += d[i] * d[i]; }
#pragma unroll
    for (int o = 16; o > 0; o >>= 1) part2 += __shfl_xor_sync(0xffffffffu, part2, o);
    const float var = part2 * (1.0f / 256.0f);
    const float inv = rsqrtf(var + 1e-5f);

    float4 gg0 = *(const float4*)(gamma + c8);
    float4 gg1 = *(const float4*)(gamma + c8 + 4);
    float4 be0 = *(const float4*)(beta + c8);
    float4 be1 = *(const float4*)(beta + c8 + 4);
    float z[8];
    z[0] = fmaxf(d[0] * inv * gg0.x + be0.x, 0.0f);
    z[1] = fmaxf(d[1] * inv * gg0.y + be0.y, 0.0f);
    z[2] = fmaxf(d[2] * inv * gg0.z + be0.z, 0.0f);
    z[3] = fmaxf(d[3] * inv * gg0.w + be0.w, 0.0f);
    z[4] = fmaxf(d[4] * inv * gg1.x + be1.x, 0.0f);
    z[5] = fmaxf(d[5] * inv * gg1.y + be1.y, 0.0f);
    z[6] = fmaxf(d[6] * inv * gg1.z + be1.z, 0.0f);
    z[7] = fmaxf(d[7] * inv * gg1.w + be1.w, 0.0f);
    *(float4*)(out + (size_t)v * CC + c8)     = make_float4(z[0], z[1], z[2], z[3]);
    *(float4*)(out + (size_t)v * CC + c8 + 4) = make_float4(z[4], z[5], z[6], z[7]);

    if (write_h) {
        __half2 hh[4];
        hh[0] = __floats2half2_rn(z[0], z[1]);
        hh[1] = __floats2half2_rn(z[2], z[3]);
        hh[2] = __floats2half2_rn(z[4], z[5]);
        hh[3] = __floats2half2_rn(z[6], z[7]);
        *(uint4*)(g_ah + (size_t)v * CC + c8) = *(uint4*)hh;
    }
}

// =============== launcher ===============
extern "C" void kernel_launch(void* const* d_in, const int* in_sizes, int n_in,
                              void* d_out, int out_size) {
    const float* x     = (const float*)d_in[0];
    const int*   edges = (const int*)d_in[1];
    const float* W1    = (const float*)d_in[2];
    const float* b1    = (const float*)d_in[3];
    const float* W2    = (const float*)d_in[4];
    const float* b2    = (const float*)d_in[5];
    const float* gamma = (const float*)d_in[6];
    const float* beta  = (const float*)d_in[7];
    float* out = (float*)d_out;

    int E = in_sizes[1] / 2;
    if (E > EE_MAX) E = EE_MAX;
    const int* row = edges;
    const int* col = edges + E;

    float* z1 = out;
    float* z2 = out + (size_t)NN * CC;

    cudaFuncSetAttribute(k_gemm_mma<false>, cudaFuncAttributeMaxDynamicSharedMemorySize, GEMM_SMEM);
    cudaFuncSetAttribute(k_gemm_mma<true>,  cudaFuncAttributeMaxDynamicSharedMemorySize, GEMM_SMEM);

    dim3 ggrid(1, MBLK);
    int ethreads = (E / 4 + 255) / 256;

    // profiled launch is index 3 -> gemm1 there
    k_conv_zero<<<512 + (NN + 255) / 256, 256>>>(W1, W2);       // 0
    k_hist<<<ethreads, 256>>>(col, E);                          // 1
    k_scan1<<<SCAN_BLK, 1024>>>();                              // 2 (+isd)
    k_gemm_mma<false><<<ggrid, 256, GEMM_SMEM>>>(x);            // 3  <- profiled
    k_scan3<<<SCAN_BLK, 1024>>>();                              // 4 (incl. level-2 scan)
    k_fill<<<ethreads, 256>>>(row, col, E);                     // 5
    k_agg_ln<<<(NN + 3) / 4, 128>>>(b1, gamma, beta, z1, 1);    // 6
    k_gemm_mma<true><<<ggrid, 256, GEMM_SMEM>>>(z1);            // 7
    k_agg_ln<<<(NN + 3) / 4, 128>>>(b2, gamma, beta, z2, 0);    // 8
}

// round 16
// speedup vs baseline: 1.0774x; 1.0774x over previous
#include <cuda_runtime.h>
#include <cuda_fp16.h>
#include <cstdint>

#define NN 100000
#define CC 256
#define EE_MAX 1600000
#define MBLK ((NN + 127) / 128)
#define SCAN_BLK 98            // ceil(100000/1024)

// ---- scratch (__device__ globals) ----
__device__ int   g_deg[NN];
__device__ int   g_off[NN + 1];
__device__ int   g_cur[NN];
__device__ int   g_src[EE_MAX];
__device__ int   g_bsum[128];
__device__ float g_isd[NN];
__device__ __half g_xs[(size_t)NN * CC];            // (h@W)*isd[node], fp16
__device__ __half g_ah[(size_t)(NN + 128) * CC];    // fp16 copy of z1 (layer-2 GEMM input)
__device__ __half g_w1[CC * CC];                    // W1^T [n][k], fp16
__device__ __half g_w2[CC * CC];                    // W2^T [n][k], fp16

// =============== launch 0: convert W (both layers, fp16) + zero deg ===============
__global__ void k_conv_zero(const float* __restrict__ W1, const float* __restrict__ W2) {
    int gi = blockIdx.x * 256 + threadIdx.x;
    if (blockIdx.x < 512) {
        const float* W = (gi < CC * CC) ? W1 : W2;
        int i = gi & (CC * CC - 1);
        int n = i >> 8, k = i & 255;
        __half h = __float2half_rn(W[k * CC + n]);
        if (gi < CC * CC) g_w1[i] = h;
        else              g_w2[i] = h;
    } else {
        int i = gi - 512 * 256;
        if (i < NN) g_deg[i] = 0;
    }
}

// 8 edges/thread histogram
__global__ void k_hist(const int* __restrict__ col, int E) {
    int e = (blockIdx.x * blockDim.x + threadIdx.x) * 8;
    if (e + 8 <= E) {
        int4 c0 = *(const int4*)(col + e);
        int4 c1 = *(const int4*)(col + e + 4);
        atomicAdd(&g_deg[c0.x], 1); atomicAdd(&g_deg[c0.y], 1);
        atomicAdd(&g_deg[c0.z], 1); atomicAdd(&g_deg[c0.w], 1);
        atomicAdd(&g_deg[c1.x], 1); atomicAdd(&g_deg[c1.y], 1);
        atomicAdd(&g_deg[c1.z], 1); atomicAdd(&g_deg[c1.w], 1);
    } else {
        for (; e < E; e++) atomicAdd(&g_deg[col[e]], 1);
    }
}

// scan level 1 + isd
__global__ void __launch_bounds__(1024) k_scan1() {
    __shared__ int sh[1024];
    int i = blockIdx.x * 1024 + threadIdx.x;
    int v = (i < NN) ? g_deg[i] : 0;
    if (i < NN) g_isd[i] = rsqrtf((float)(v + 1));
    sh[threadIdx.x] = v;
    __syncthreads();
    for (int o = 512; o > 0; o >>= 1) {
        if (threadIdx.x < o) sh[threadIdx.x] += sh[threadIdx.x + o];
        __syncthreads();
    }
    if (threadIdx.x == 0) g_bsum[blockIdx.x] = sh[0];
}
// scan level 2 folded into level 3
__global__ void __launch_bounds__(1024) k_scan3() {
    __shared__ int sh[1024];
    __shared__ int sb[128];
    __shared__ int base_s;
    if (threadIdx.x < 128) sb[threadIdx.x] = (threadIdx.x < SCAN_BLK) ? g_bsum[threadIdx.x] : 0;
    __syncthreads();
    if (threadIdx.x == 0) {
        int c = 0;
        for (int j = 0; j < (int)blockIdx.x; j++) c += sb[j];
        base_s = c;
        if (blockIdx.x == 0) {
            int tot = 0;
            for (int j = 0; j < SCAN_BLK; j++) tot += sb[j];
            g_off[NN] = tot;
        }
    }
    int i = blockIdx.x * 1024 + threadIdx.x;
    int v = (i < NN) ? g_deg[i] : 0;
    sh[threadIdx.x] = v;
    __syncthreads();
    for (int o = 1; o < 1024; o <<= 1) {
        int u = (threadIdx.x >= o) ? sh[threadIdx.x - o] : 0;
        __syncthreads();
        sh[threadIdx.x] += u;
        __syncthreads();
    }
    if (i < NN) {
        int excl = base_s + sh[threadIdx.x] - v;
        g_off[i] = excl;
        g_cur[i] = excl;
    }
}
// 8 edges/thread fill
__global__ void k_fill(const int* __restrict__ row, const int* __restrict__ col, int E) {
    int e = (blockIdx.x * blockDim.x + threadIdx.x) * 8;
    if (e + 8 <= E) {
        int4 r0 = *(const int4*)(row + e);
        int4 r1 = *(const int4*)(row + e + 4);
        int4 c0 = *(const int4*)(col + e);
        int4 c1 = *(const int4*)(col + e + 4);
        int p0 = atomicAdd(&g_cur[c0.x], 1); if (p0 < EE_MAX) g_src[p0] = r0.x;
        int p1 = atomicAdd(&g_cur[c0.y], 1); if (p1 < EE_MAX) g_src[p1] = r0.y;
        int p2 = atomicAdd(&g_cur[c0.z], 1); if (p2 < EE_MAX) g_src[p2] = r0.z;
        int p3 = atomicAdd(&g_cur[c0.w], 1); if (p3 < EE_MAX) g_src[p3] = r0.w;
        int p4 = atomicAdd(&g_cur[c1.x], 1); if (p4 < EE_MAX) g_src[p4] = r1.x;
        int p5 = atomicAdd(&g_cur[c1.y], 1); if (p5 < EE_MAX) g_src[p5] = r1.y;
        int p6 = atomicAdd(&g_cur[c1.z], 1); if (p6 < EE_MAX) g_src[p6] = r1.z;
        int p7 = atomicAdd(&g_cur[c1.w], 1); if (p7 < EE_MAX) g_src[p7] = r1.w;
    } else {
        for (; e < E; e++) {
            int pos = atomicAdd(&g_cur[col[e]], 1);
            if (pos < EE_MAX) g_src[pos] = row[e];
        }
    }
}

// =============== warp-MMA GEMM: 128x128, 2 CTA/SM (round-14 config) ===============
#define KPAD 40            // fp16 row stride 80B -> ldmatrix conflict-free
#define ABUF (128 * KPAD)
#define BUFSTR (2 * ABUF)

__device__ __forceinline__ void mma_f16(float* c, const uint32_t* a, const uint32_t* b) {
    asm volatile(
        "mma.sync.aligned.m16n8k16.row.col.f32.f16.f16.f32 "
        "{%0,%1,%2,%3}, {%4,%5,%6,%7}, {%8,%9}, {%0,%1,%2,%3};"
        : "+f"(c[0]), "+f"(c[1]), "+f"(c[2]), "+f"(c[3])
        : "r"(a[0]), "r"(a[1]), "r"(a[2]), "r"(a[3]), "r"(b[0]), "r"(b[1]));
}
__device__ __forceinline__ void ldsm4(uint32_t* r, uint32_t a) {
    asm volatile("ldmatrix.sync.aligned.m8n8.x4.shared.b16 {%0,%1,%2,%3}, [%4];"
                 : "=r"(r[0]), "=r"(r[1]), "=r"(r[2]), "=r"(r[3]) : "r"(a));
}
__device__ __forceinline__ void cpasync16(uint32_t dst, const void* src) {
    asm volatile("cp.async.cg.shared.global [%0], [%1], 16;" :: "r"(dst), "l"(src));
}
#define CP_COMMIT() asm volatile("cp.async.commit_group;" ::: "memory")
#define CP_WAIT0()  asm volatile("cp.async.wait_group 0;" ::: "memory")

template <bool HALF_A>
__global__ void __launch_bounds__(256, 2) k_gemm_mma(const float* __restrict__ A) {
    const __half* __restrict__ W = HALF_A ? g_w2 : g_w1;

    extern __shared__ __half smem[];
    const uint32_t sbase = (uint32_t)__cvta_generic_to_shared(smem);

    const int tid = threadIdx.x;
    const int wid = tid >> 5;
    const int lane = tid & 31;
    const int brow = blockIdx.y * 128;
    const int bcol = blockIdx.x * 128;
    const int wm = (wid & 3) * 32;
    const int wn = (wid >> 2) * 64;

    float acc[2][8][4];
#pragma unroll
    for (int i = 0; i < 2; i++)
#pragma unroll
        for (int j = 0; j < 8; j++)
#pragma unroll
            for (int l = 0; l < 4; l++) acc[i][j][l] = 0.0f;

    const int ar = tid >> 1;
    const int aq = tid & 1;
    const int br = tid >> 2;
    const int bq = tid & 3;
    const bool arow_ok = (brow + ar) < NN;
    const float* Abase = A + (size_t)(brow + ar) * CC;
    const int ahr = tid >> 2;
    const __half* AHbase = g_ah + (size_t)(brow + ahr) * CC + bq * 8;
    const uint32_t asto = (uint32_t)(ahr * (KPAD * 2) + bq * 16);
    const uint32_t bsto = (uint32_t)(br * (KPAD * 2) + bq * 16);

    const uint32_t aoff = (uint32_t)((wm + (lane & 15)) * (KPAD * 2) + ((lane >> 4) * 8) * 2);
    const uint32_t boff = (uint32_t)((wn + (lane & 7) + ((lane >> 4) & 1) * 8) * (KPAD * 2)
                                     + (((lane >> 3) & 1) * 8) * 2);

    float4 pf[4];
#pragma unroll
    for (int p = 0; p < 4; p++) pf[p] = make_float4(0.f, 0.f, 0.f, 0.f);

    if (!HALF_A) {
        if (arow_ok) {
#pragma unroll
            for (int p = 0; p < 4; p++) pf[p] = *(const float4*)(Abase + (aq + p * 2) * 4);
        }
    } else {
#pragma unroll
        for (int p = 0; p < 2; p++)
            cpasync16(sbase + asto + p * 64 * (KPAD * 2), AHbase + (size_t)(p * 64) * CC);
    }
    {
        const uint32_t b0 = sbase + ABUF * 2;
#pragma unroll
        for (int p = 0; p < 2; p++) {
            size_t so = (size_t)(bcol + br + p * 64) * CC + bq * 8;
            cpasync16(b0 + bsto + p * 64 * (KPAD * 2), W + so);
        }
        CP_COMMIT();
    }

    for (int kc = 0; kc < 8; kc++) {
        const uint32_t cb = (uint32_t)(kc & 1) * BUFSTR * 2;
        __half* As = smem + (kc & 1) * BUFSTR;

        if (!HALF_A) {
#pragma unroll
            for (int p = 0; p < 4; p++) {
                int q = aq + p * 2;
                float4 v = pf[p];
                *(__half2*)(As + ar * KPAD + q * 4)     = __floats2half2_rn(v.x, v.y);
                *(__half2*)(As + ar * KPAD + q * 4 + 2) = __floats2half2_rn(v.z, v.w);
            }
        }
        CP_WAIT0();
        __syncthreads();

        if (kc < 7) {
            const int k1 = (kc + 1) * 32;
            const uint32_t ob = (uint32_t)((kc + 1) & 1) * BUFSTR * 2;
            if (!HALF_A) {
                if (arow_ok) {
#pragma unroll
                    for (int p = 0; p < 4; p++)
                        pf[p] = *(const float4*)(Abase + k1 + (aq + p * 2) * 4);
                }
            } else {
#pragma unroll
                for (int p = 0; p < 2; p++)
                    cpasync16(sbase + ob + asto + p * 64 * (KPAD * 2),
                              AHbase + (size_t)(p * 64) * CC + k1);
            }
            const uint32_t nb = sbase + ob + ABUF * 2;
#pragma unroll
            for (int p = 0; p < 2; p++) {
                size_t so = (size_t)(bcol + br + p * 64) * CC + k1 + bq * 8;
                cpasync16(nb + bsto + p * 64 * (KPAD * 2), W + so);
            }
            CP_COMMIT();
        }

        const uint32_t sA = sbase + cb;
        const uint32_t sB = sbase + cb + ABUF * 2;
#pragma unroll
        for (int ks = 0; ks < 32; ks += 16) {
            const uint32_t ksb = (uint32_t)(ks * 2);
            uint32_t ah[2][4];
            ldsm4(ah[0], sA + aoff + ksb);
            ldsm4(ah[1], sA + aoff + 16 * (KPAD * 2) + ksb);
#pragma unroll
            for (int nfp = 0; nfp < 4; nfp++) {
                uint32_t bh[4];
                ldsm4(bh, sB + boff + nfp * 16 * (KPAD * 2) + ksb);
#pragma unroll
                for (int half = 0; half < 2; half++) {
                    int nf = nfp * 2 + half;
#pragma unroll
                    for (int mf = 0; mf < 2; mf++)
                        mma_f16(acc[mf][nf], ah[mf], bh + half * 2);
                }
            }
        }
    }

    const int fr = lane >> 2;
    const int fc = (lane & 3) * 2;
#pragma unroll
    for (int mf = 0; mf < 2; mf++) {
#pragma unroll
        for (int half = 0; half < 2; half++) {
            int grow = brow + wm + mf * 16 + half * 8 + fr;
            if (grow < NN) {
                float s = g_isd[grow];
                __half* dst = g_xs + (size_t)grow * CC + bcol + wn + fc;
#pragma unroll
                for (int nf = 0; nf < 8; nf++) {
                    *(__half2*)(dst + nf * 8) = __floats2half2_rn(
                        acc[mf][nf][half * 2 + 0] * s,
                        acc[mf][nf][half * 2 + 1] * s);
                }
            }
        }
    }
}
#define GEMM_SMEM (2 * BUFSTR * 2)    // 40960 bytes

// =============== aggregation + LayerNorm + ReLU (4 warps/block, warp per node) ===============
__device__ __forceinline__ void add8h(float* a, uint4 v) {
    const __half2* h = (const __half2*)&v;
#pragma unroll
    for (int i = 0; i < 4; i++) {
        float2 f = __half22float2(h[i]);
        a[2 * i]     += f.x;
        a[2 * i + 1] += f.y;
    }
}

template <bool WRITE_H>
__global__ void __launch_bounds__(128) k_agg_ln(const float* __restrict__ b,
                                                const float* __restrict__ gamma,
                                                const float* __restrict__ beta,
                                                float* __restrict__ out) {
    const int v = blockIdx.x * 4 + (threadIdx.x >> 5);
    if (v >= NN) return;
    const int t = threadIdx.x & 31;
    const int c8 = t * 8;

    const uint4* xs16 = (const uint4*)g_xs;
    float acc[8];
#pragma unroll
    for (int i = 0; i < 8; i++) acc[i] = 0.0f;
    add8h(acc, xs16[(size_t)v * 32 + t]);

    int e = g_off[v];
    const int end = g_off[v + 1];
    for (; e + 8 <= end; e += 8) {
        uint4 x0 = xs16[(size_t)g_src[e]     * 32 + t];
        uint4 x1 = xs16[(size_t)g_src[e + 1] * 32 + t];
        uint4 x2 = xs16[(size_t)g_src[e + 2] * 32 + t];
        uint4 x3 = xs16[(size_t)g_src[e + 3] * 32 + t];
        uint4 x4 = xs16[(size_t)g_src[e + 4] * 32 + t];
        uint4 x5 = xs16[(size_t)g_src[e + 5] * 32 + t];
        uint4 x6 = xs16[(size_t)g_src[e + 6] * 32 + t];
        uint4 x7 = xs16[(size_t)g_src[e + 7] * 32 + t];
        add8h(acc, x0); add8h(acc, x1); add8h(acc, x2); add8h(acc, x3);
        add8h(acc, x4); add8h(acc, x5); add8h(acc, x6); add8h(acc, x7);
    }
    for (; e < end; e++) add8h(acc, xs16[(size_t)g_src[e] * 32 + t]);

    const float s = g_isd[v];
    float4 bb0 = *(const float4*)(b + c8);
    float4 bb1 = *(const float4*)(b + c8 + 4);
    float h[8];
    h[0] = acc[0] * s + bb0.x; h[1] = acc[1] * s + bb0.y;
    h[2] = acc[2] * s + bb0.z; h[3] = acc[3] * s + bb0.w;
    h[4] = acc[4] * s + bb1.x; h[5] = acc[5] * s + bb1.y;
    h[6] = acc[6] * s + bb1.z; h[7] = acc[7] * s + bb1.w;

    float part = 0.f;
#pragma unroll
    for (int i = 0; i < 8; i++) part += h[i];
#pragma unroll
    for (int o = 16; o > 0; o >>= 1) part += __shfl_xor_sync(0xffffffffu, part, o);
    const float mu = part * (1.0f / 256.0f);

    float d[8];
    float part2 = 0.f;
#pragma unroll
    for (int i = 0; i < 8; i++) { d[i] = h[i] - mu; part2 += d[i] * d[i]; }
#pragma unroll
    for (int o = 16; o > 0; o >>= 1) part2 += __shfl_xor_sync(0xffffffffu, part2, o);
    const float var = part2 * (1.0f / 256.0f);
    const float inv = rsqrtf(var + 1e-5f);

    float4 gg0 = *(const float4*)(gamma + c8);
    float4 gg1 = *(const float4*)(gamma + c8 + 4);
    float4 be0 = *(const float4*)(beta + c8);
    float4 be1 = *(const float4*)(beta + c8 + 4);
    float z[8];
    z[0] = fmaxf(d[0] * inv * gg0.x + be0.x, 0.0f);
    z[1] = fmaxf(d[1] * inv * gg0.y + be0.y, 0.0f);
    z[2] = fmaxf(d[2] * inv * gg0.z + be0.z, 0.0f);
    z[3] = fmaxf(d[3] * inv * gg0.w + be0.w, 0.0f);
    z[4] = fmaxf(d[4] * inv * gg1.x + be1.x, 0.0f);
    z[5] = fmaxf(d[5] * inv * gg1.y + be1.y, 0.0f);
    z[6] = fmaxf(d[6] * inv * gg1.z + be1.z, 0.0f);
    z[7] = fmaxf(d[7] * inv * gg1.w + be1.w, 0.0f);
    *(float4*)(out + (size_t)v * CC + c8)     = make_float4(z[0], z[1], z[2], z[3]);
    *(float4*)(out + (size_t)v * CC + c8 + 4) = make_float4(z[4], z[5], z[6], z[7]);

    if (WRITE_H) {
        __half2 hh[4];
        hh[0] = __floats2half2_rn(z[0], z[1]);
        hh[1] = __floats2half2_rn(z[2], z[3]);
        hh[2] = __floats2half2_rn(z[4], z[5]);
        hh[3] = __floats2half2_rn(z[6], z[7]);
        *(uint4*)(g_ah + (size_t)v * CC + c8) = *(uint4*)hh;
    }
}

// =============== launcher ===============
extern "C" void kernel_launch(void* const* d_in, const int* in_sizes, int n_in,
                              void* d_out, int out_size) {
    const float* x     = (const float*)d_in[0];
    const int*   edges = (const int*)d_in[1];
    const float* W1    = (const float*)d_in[2];
    const float* b1    = (const float*)d_in[3];
    const float* W2    = (const float*)d_in[4];
    const float* b2    = (const float*)d_in[5];
    const float* gamma = (const float*)d_in[6];
    const float* beta  = (const float*)d_in[7];
    float* out = (float*)d_out;

    int E = in_sizes[1] / 2;
    if (E > EE_MAX) E = EE_MAX;
    const int* row = edges;
    const int* col = edges + E;

    float* z1 = out;
    float* z2 = out + (size_t)NN * CC;

    cudaFuncSetAttribute(k_gemm_mma<false>, cudaFuncAttributeMaxDynamicSharedMemorySize, GEMM_SMEM);
    cudaFuncSetAttribute(k_gemm_mma<true>,  cudaFuncAttributeMaxDynamicSharedMemorySize, GEMM_SMEM);

    dim3 ggrid(2, MBLK);
    int ethreads = (E / 8 + 255) / 256;

    // profiled launch is index 3 -> gemm1 there
    k_conv_zero<<<512 + (NN + 255) / 256, 256>>>(W1, W2);           // 0
    k_hist<<<ethreads, 256>>>(col, E);                              // 1
    k_scan1<<<SCAN_BLK, 1024>>>();                                  // 2 (+isd)
    k_gemm_mma<false><<<ggrid, 256, GEMM_SMEM>>>(x);                // 3  <- profiled
    k_scan3<<<SCAN_BLK, 1024>>>();                                  // 4 (incl. level-2 scan)
    k_fill<<<ethreads, 256>>>(row, col, E);                         // 5
    k_agg_ln<true><<<(NN + 3) / 4, 128>>>(b1, gamma, beta, z1);     // 6
    k_gemm_mma<true><<<ggrid, 256, GEMM_SMEM>>>(z1);                // 7
    k_agg_ln<false><<<(NN + 3) / 4, 128>>>(b2, gamma, beta, z2);    // 8
}

// round 17
// speedup vs baseline: 1.0925x; 1.0140x over previous
#include <cuda_runtime.h>
#include <cuda_fp16.h>
#include <cstdint>

#define NN 100000
#define CC 256
#define EE_MAX 1600000
#define MBLK ((NN + 127) / 128)
#define SCAN_BLK 98            // ceil(100000/1024)

// ---- scratch (__device__ globals) ----
__device__ int   g_deg[NN];
__device__ int   g_off[NN + 1];
__device__ int   g_cur[NN];
__device__ int   g_src[EE_MAX];
__device__ int   g_bsum[128];
__device__ float g_isd[NN];
__device__ __half g_xs[(size_t)NN * CC];            // (h@W)*isd[node], fp16
__device__ __half g_ah[(size_t)(NN + 128) * CC];    // fp16 copy of z1 (layer-2 GEMM input)
__device__ __half g_w1[CC * CC];                    // W1^T [n][k], fp16
__device__ __half g_w2[CC * CC];                    // W2^T [n][k], fp16

// =============== launch 0: zero deg ===============
__global__ void k_zero(){
    int i = blockIdx.x * 256 + threadIdx.x;
    if (i < NN) g_deg[i] = 0;
}

// 4 edges/thread histogram (measured optimum)
__global__ void k_hist(const int* __restrict__ col, int E) {
    int e = (blockIdx.x * blockDim.x + threadIdx.x) * 4;
    if (e + 4 <= E) {
        int4 c = *(const int4*)(col + e);
        atomicAdd(&g_deg[c.x], 1);
        atomicAdd(&g_deg[c.y], 1);
        atomicAdd(&g_deg[c.z], 1);
        atomicAdd(&g_deg[c.w], 1);
    } else {
        for (; e < E; e++) atomicAdd(&g_deg[col[e]], 1);
    }
}

// scan level 1 + isd; extra blocks convert W1/W2 (independent work, same launch)
__global__ void __launch_bounds__(1024) k_scan1(const float* __restrict__ W1,
                                                const float* __restrict__ W2) {
    if (blockIdx.x >= SCAN_BLK) {
        // W conversion: 128 blocks x 1024 threads = 131072 = 2*65536 elements
        int gi = (blockIdx.x - SCAN_BLK) * 1024 + threadIdx.x;
        const float* W = (gi < CC * CC) ? W1 : W2;
        int i = gi & (CC * CC - 1);
        int n = i >> 8, k = i & 255;
        __half h = __float2half_rn(W[k * CC + n]);
        if (gi < CC * CC) g_w1[i] = h;
        else              g_w2[i] = h;
        return;
    }
    __shared__ int sh[1024];
    int i = blockIdx.x * 1024 + threadIdx.x;
    int v = (i < NN) ? g_deg[i] : 0;
    if (i < NN) g_isd[i] = rsqrtf((float)(v + 1));
    sh[threadIdx.x] = v;
    __syncthreads();
    for (int o = 512; o > 0; o >>= 1) {
        if (threadIdx.x < o) sh[threadIdx.x] += sh[threadIdx.x + o];
        __syncthreads();
    }
    if (threadIdx.x == 0) g_bsum[blockIdx.x] = sh[0];
}
// scan level 2 folded into level 3
__global__ void __launch_bounds__(1024) k_scan3() {
    __shared__ int sh[1024];
    __shared__ int sb[128];
    __shared__ int base_s;
    if (threadIdx.x < 128) sb[threadIdx.x] = (threadIdx.x < SCAN_BLK) ? g_bsum[threadIdx.x] : 0;
    __syncthreads();
    if (threadIdx.x == 0) {
        int c = 0;
        for (int j = 0; j < (int)blockIdx.x; j++) c += sb[j];
        base_s = c;
        if (blockIdx.x == 0) {
            int tot = 0;
            for (int j = 0; j < SCAN_BLK; j++) tot += sb[j];
            g_off[NN] = tot;
        }
    }
    int i = blockIdx.x * 1024 + threadIdx.x;
    int v = (i < NN) ? g_deg[i] : 0;
    sh[threadIdx.x] = v;
    __syncthreads();
    for (int o = 1; o < 1024; o <<= 1) {
        int u = (threadIdx.x >= o) ? sh[threadIdx.x - o] : 0;
        __syncthreads();
        sh[threadIdx.x] += u;
        __syncthreads();
    }
    if (i < NN) {
        int excl = base_s + sh[threadIdx.x] - v;
        g_off[i] = excl;
        g_cur[i] = excl;
    }
}
// 4 edges/thread fill (measured optimum)
__global__ void k_fill(const int* __restrict__ row, const int* __restrict__ col, int E) {
    int e = (blockIdx.x * blockDim.x + threadIdx.x) * 4;
    if (e + 4 <= E) {
        int4 r = *(const int4*)(row + e);
        int4 c = *(const int4*)(col + e);
        int p0 = atomicAdd(&g_cur[c.x], 1); if (p0 < EE_MAX) g_src[p0] = r.x;
        int p1 = atomicAdd(&g_cur[c.y], 1); if (p1 < EE_MAX) g_src[p1] = r.y;
        int p2 = atomicAdd(&g_cur[c.z], 1); if (p2 < EE_MAX) g_src[p2] = r.z;
        int p3 = atomicAdd(&g_cur[c.w], 1); if (p3 < EE_MAX) g_src[p3] = r.w;
    } else {
        for (; e < E; e++) {
            int pos = atomicAdd(&g_cur[col[e]], 1);
            if (pos < EE_MAX) g_src[pos] = row[e];
        }
    }
}

// =============== warp-MMA GEMM: 128x128, 2 CTA/SM ===============
#define KPAD 40            // fp16 row stride 80B -> ldmatrix conflict-free
#define ABUF (128 * KPAD)
#define BUFSTR (2 * ABUF)

__device__ __forceinline__ void mma_f16(float* c, const uint32_t* a, const uint32_t* b) {
    asm volatile(
        "mma.sync.aligned.m16n8k16.row.col.f32.f16.f16.f32 "
        "{%0,%1,%2,%3}, {%4,%5,%6,%7}, {%8,%9}, {%0,%1,%2,%3};"
        : "+f"(c[0]), "+f"(c[1]), "+f"(c[2]), "+f"(c[3])
        : "r"(a[0]), "r"(a[1]), "r"(a[2]), "r"(a[3]), "r"(b[0]), "r"(b[1]));
}
__device__ __forceinline__ void ldsm4(uint32_t* r, uint32_t a) {
    asm volatile("ldmatrix.sync.aligned.m8n8.x4.shared.b16 {%0,%1,%2,%3}, [%4];"
                 : "=r"(r[0]), "=r"(r[1]), "=r"(r[2]), "=r"(r[3]) : "r"(a));
}
__device__ __forceinline__ void cpasync16(uint32_t dst, const void* src) {
    asm volatile("cp.async.cg.shared.global [%0], [%1], 16;" :: "r"(dst), "l"(src));
}
#define CP_COMMIT() asm volatile("cp.async.commit_group;" ::: "memory")
#define CP_WAIT0()  asm volatile("cp.async.wait_group 0;" ::: "memory")

template <bool HALF_A>
__global__ void __launch_bounds__(256, 2) k_gemm_mma(const float* __restrict__ A) {
    const __half* __restrict__ W = HALF_A ? g_w2 : g_w1;

    extern __shared__ __half smem[];
    const uint32_t sbase = (uint32_t)__cvta_generic_to_shared(smem);

    const int tid = threadIdx.x;
    const int wid = tid >> 5;
    const int lane = tid & 31;
    const int brow = blockIdx.y * 128;
    const int bcol = blockIdx.x * 128;
    const int wm = (wid & 3) * 32;
    const int wn = (wid >> 2) * 64;

    float acc[2][8][4];
#pragma unroll
    for (int i = 0; i < 2; i++)
#pragma unroll
        for (int j = 0; j < 8; j++)
#pragma unroll
            for (int l = 0; l < 4; l++) acc[i][j][l] = 0.0f;

    const int ar = tid >> 1;
    const int aq = tid & 1;
    const int br = tid >> 2;
    const int bq = tid & 3;
    const bool arow_ok = (brow + ar) < NN;
    const float* Abase = A + (size_t)(brow + ar) * CC;
    const int ahr = tid >> 2;
    const __half* AHbase = g_ah + (size_t)(brow + ahr) * CC + bq * 8;
    const uint32_t asto = (uint32_t)(ahr * (KPAD * 2) + bq * 16);
    const uint32_t bsto = (uint32_t)(br * (KPAD * 2) + bq * 16);

    const uint32_t aoff = (uint32_t)((wm + (lane & 15)) * (KPAD * 2) + ((lane >> 4) * 8) * 2);
    const uint32_t boff = (uint32_t)((wn + (lane & 7) + ((lane >> 4) & 1) * 8) * (KPAD * 2)
                                     + (((lane >> 3) & 1) * 8) * 2);

    float4 pf[4];
#pragma unroll
    for (int p = 0; p < 4; p++) pf[p] = make_float4(0.f, 0.f, 0.f, 0.f);

    if (!HALF_A) {
        if (arow_ok) {
#pragma unroll
            for (int p = 0; p < 4; p++) pf[p] = *(const float4*)(Abase + (aq + p * 2) * 4);
        }
    } else {
#pragma unroll
        for (int p = 0; p < 2; p++)
            cpasync16(sbase + asto + p * 64 * (KPAD * 2), AHbase + (size_t)(p * 64) * CC);
    }
    {
        const uint32_t b0 = sbase + ABUF * 2;
#pragma unroll
        for (int p = 0; p < 2; p++) {
            size_t so = (size_t)(bcol + br + p * 64) * CC + bq * 8;
            cpasync16(b0 + bsto + p * 64 * (KPAD * 2), W + so);
        }
        CP_COMMIT();
    }

    for (int kc = 0; kc < 8; kc++) {
        const uint32_t cb = (uint32_t)(kc & 1) * BUFSTR * 2;
        __half* As = smem + (kc & 1) * BUFSTR;

        if (!HALF_A) {
#pragma unroll
            for (int p = 0; p < 4; p++) {
                int q = aq + p * 2;
                float4 v = pf[p];
                *(__half2*)(As + ar * KPAD + q * 4)     = __floats2half2_rn(v.x, v.y);
                *(__half2*)(As + ar * KPAD + q * 4 + 2) = __floats2half2_rn(v.z, v.w);
            }
        }
        CP_WAIT0();
        __syncthreads();

        if (kc < 7) {
            const int k1 = (kc + 1) * 32;
            const uint32_t ob = (uint32_t)((kc + 1) & 1) * BUFSTR * 2;
            if (!HALF_A) {
                if (arow_ok) {
#pragma unroll
                    for (int p = 0; p < 4; p++)
                        pf[p] = *(const float4*)(Abase + k1 + (aq + p * 2) * 4);
                }
            } else {
#pragma unroll
                for (int p = 0; p < 2; p++)
                    cpasync16(sbase + ob + asto + p * 64 * (KPAD * 2),
                              AHbase + (size_t)(p * 64) * CC + k1);
            }
            const uint32_t nb = sbase + ob + ABUF * 2;
#pragma unroll
            for (int p = 0; p < 2; p++) {
                size_t so = (size_t)(bcol + br + p * 64) * CC + k1 + bq * 8;
                cpasync16(nb + bsto + p * 64 * (KPAD * 2), W + so);
            }
            CP_COMMIT();
        }

        const uint32_t sA = sbase + cb;
        const uint32_t sB = sbase + cb + ABUF * 2;
#pragma unroll
        for (int ks = 0; ks < 32; ks += 16) {
            const uint32_t ksb = (uint32_t)(ks * 2);
            uint32_t ah[2][4];
            ldsm4(ah[0], sA + aoff + ksb);
            ldsm4(ah[1], sA + aoff + 16 * (KPAD * 2) + ksb);
#pragma unroll
            for (int nfp = 0; nfp < 4; nfp++) {
                uint32_t bh[4];
                ldsm4(bh, sB + boff + nfp * 16 * (KPAD * 2) + ksb);
#pragma unroll
                for (int half = 0; half < 2; half++) {
                    int nf = nfp * 2 + half;
#pragma unroll
                    for (int mf = 0; mf < 2; mf++)
                        mma_f16(acc[mf][nf], ah[mf], bh + half * 2);
                }
            }
        }
    }

    const int fr = lane >> 2;
    const int fc = (lane & 3) * 2;
#pragma unroll
    for (int mf = 0; mf < 2; mf++) {
#pragma unroll
        for (int half = 0; half < 2; half++) {
            int grow = brow + wm + mf * 16 + half * 8 + fr;
            if (grow < NN) {
                float s = g_isd[grow];
                __half* dst = g_xs + (size_t)grow * CC + bcol + wn + fc;
#pragma unroll
                for (int nf = 0; nf < 8; nf++) {
                    *(__half2*)(dst + nf * 8) = __floats2half2_rn(
                        acc[mf][nf][half * 2 + 0] * s,
                        acc[mf][nf][half * 2 + 1] * s);
                }
            }
        }
    }
}
#define GEMM_SMEM (2 * BUFSTR * 2)    // 40960 bytes

// =============== aggregation + LayerNorm + ReLU (4 warps/block, warp per node) ===============
__device__ __forceinline__ void add8h(float* a, uint4 v) {
    const __half2* h = (const __half2*)&v;
#pragma unroll
    for (int i = 0; i < 4; i++) {
        float2 f = __half22float2(h[i]);
        a[2 * i]     += f.x;
        a[2 * i + 1] += f.y;
    }
}

template <bool WRITE_H>
__global__ void __launch_bounds__(128) k_agg_ln(const float* __restrict__ b,
                                                const float* __restrict__ gamma,
                                                const float* __restrict__ beta,
                                                float* __restrict__ out) {
    const int v = blockIdx.x * 4 + (threadIdx.x >> 5);
    if (v >= NN) return;
    const int t = threadIdx.x & 31;
    const int c8 = t * 8;

    const uint4* xs16 = (const uint4*)g_xs;
    float acc[8];
#pragma unroll
    for (int i = 0; i < 8; i++) acc[i] = 0.0f;
    add8h(acc, xs16[(size_t)v * 32 + t]);

    int e = g_off[v];
    const int end = g_off[v + 1];
    for (; e + 8 <= end; e += 8) {
        uint4 x0 = xs16[(size_t)g_src[e]     * 32 + t];
        uint4 x1 = xs16[(size_t)g_src[e + 1] * 32 + t];
        uint4 x2 = xs16[(size_t)g_src[e + 2] * 32 + t];
        uint4 x3 = xs16[(size_t)g_src[e + 3] * 32 + t];
        uint4 x4 = xs16[(size_t)g_src[e + 4] * 32 + t];
        uint4 x5 = xs16[(size_t)g_src[e + 5] * 32 + t];
        uint4 x6 = xs16[(size_t)g_src[e + 6] * 32 + t];
        uint4 x7 = xs16[(size_t)g_src[e + 7] * 32 + t];
        add8h(acc, x0); add8h(acc, x1); add8h(acc, x2); add8h(acc, x3);
        add8h(acc, x4); add8h(acc, x5); add8h(acc, x6); add8h(acc, x7);
    }
    for (; e < end; e++) add8h(acc, xs16[(size_t)g_src[e] * 32 + t]);

    const float s = g_isd[v];
    float4 bb0 = *(const float4*)(b + c8);
    float4 bb1 = *(const float4*)(b + c8 + 4);
    float h[8];
    h[0] = acc[0] * s + bb0.x; h[1] = acc[1] * s + bb0.y;
    h[2] = acc[2] * s + bb0.z; h[3] = acc[3] * s + bb0.w;
    h[4] = acc[4] * s + bb1.x; h[5] = acc[5] * s + bb1.y;
    h[6] = acc[6] * s + bb1.z; h[7] = acc[7] * s + bb1.w;

    float part = 0.f;
#pragma unroll
    for (int i = 0; i < 8; i++) part += h[i];
#pragma unroll
    for (int o = 16; o > 0; o >>= 1) part += __shfl_xor_sync(0xffffffffu, part, o);
    const float mu = part * (1.0f / 256.0f);

    float d[8];
    float part2 = 0.f;
#pragma unroll
    for (int i = 0; i < 8; i++) { d[i] = h[i] - mu; part2 += d[i] * d[i]; }
#pragma unroll
    for (int o = 16; o > 0; o >>= 1) part2 += __shfl_xor_sync(0xffffffffu, part2, o);
    const float var = part2 * (1.0f / 256.0f);
    const float inv = rsqrtf(var + 1e-5f);

    float4 gg0 = *(const float4*)(gamma + c8);
    float4 gg1 = *(const float4*)(gamma + c8 + 4);
    float4 be0 = *(const float4*)(beta + c8);
    float4 be1 = *(const float4*)(beta + c8 + 4);
    float z[8];
    z[0] = fmaxf(d[0] * inv * gg0.x + be0.x, 0.0f);
    z[1] = fmaxf(d[1] * inv * gg0.y + be0.y, 0.0f);
    z[2] = fmaxf(d[2] * inv * gg0.z + be0.z, 0.0f);
    z[3] = fmaxf(d[3] * inv * gg0.w + be0.w, 0.0f);
    z[4] = fmaxf(d[4] * inv * gg1.x + be1.x, 0.0f);
    z[5] = fmaxf(d[5] * inv * gg1.y + be1.y, 0.0f);
    z[6] = fmaxf(d[6] * inv * gg1.z + be1.z, 0.0f);
    z[7] = fmaxf(d[7] * inv * gg1.w + be1.w, 0.0f);
    *(float4*)(out + (size_t)v * CC + c8)     = make_float4(z[0], z[1], z[2], z[3]);
    *(float4*)(out + (size_t)v * CC + c8 + 4) = make_float4(z[4], z[5], z[6], z[7]);

    if (WRITE_H) {
        __half2 hh[4];
        hh[0] = __floats2half2_rn(z[0], z[1]);
        hh[1] = __floats2half2_rn(z[2], z[3]);
        hh[2] = __floats2half2_rn(z[4], z[5]);
        hh[3] = __floats2half2_rn(z[6], z[7]);
        *(uint4*)(g_ah + (size_t)v * CC + c8) = *(uint4*)hh;
    }
}

// =============== launcher ===============
extern "C" void kernel_launch(void* const* d_in, const int* in_sizes, int n_in,
                              void* d_out, int out_size) {
    const float* x     = (const float*)d_in[0];
    const int*   edges = (const int*)d_in[1];
    const float* W1    = (const float*)d_in[2];
    const float* b1    = (const float*)d_in[3];
    const float* W2    = (const float*)d_in[4];
    const float* b2    = (const float*)d_in[5];
    const float* gamma = (const float*)d_in[6];
    const float* beta  = (const float*)d_in[7];
    float* out = (float*)d_out;

    int E = in_sizes[1] / 2;
    if (E > EE_MAX) E = EE_MAX;
    const int* row = edges;
    const int* col = edges + E;

    float* z1 = out;
    float* z2 = out + (size_t)NN * CC;

    cudaFuncSetAttribute(k_gemm_mma<false>, cudaFuncAttributeMaxDynamicSharedMemorySize, GEMM_SMEM);
    cudaFuncSetAttribute(k_gemm_mma<true>,  cudaFuncAttributeMaxDynamicSharedMemorySize, GEMM_SMEM);

    dim3 ggrid(2, MBLK);
    int ethreads = (E / 4 + 255) / 256;

    // profiled launch is index 3 -> gemm1 there
    k_zero<<<(NN + 255) / 256, 256>>>();                            // 0
    k_hist<<<ethreads, 256>>>(col, E);                              // 1
    k_scan1<<<SCAN_BLK + 128, 1024>>>(W1, W2);                      // 2 (+isd, +W convert)
    k_gemm_mma<false><<<ggrid, 256, GEMM_SMEM>>>(x);                // 3  <- profiled
    k_scan3<<<SCAN_BLK, 1024>>>();                                  // 4 (incl. level-2 scan)
    k_fill<<<ethreads, 256>>>(row, col, E);                         // 5
    k_agg_ln<true><<<(NN + 3) / 4, 128>>>(b1, gamma, beta, z1);     // 6
    k_gemm_mma<true><<<ggrid, 256, GEMM_SMEM>>>(z1);                // 7
    k_agg_ln<false><<<(NN + 3) / 4, 128>>>(b2, gamma, beta, z2);    // 8
}